// round 17
// baseline (speedup 1.0000x reference)
#include <cuda_runtime.h>
#include <cuda_fp16.h>
#include <stdint.h>

// ============================================================================
// TAGNet: 3x TAGConv(K=2) with dropout(0.5, jax threefry key 42) + PReLU
// N=50000 nodes, E=800000 edges, 64 -> 64 -> 64 -> 1
// R17: single-atomic-pass preprocessing (rank-based counting sort, segment-sum
//      degrees), shuffle scans. fp16 features, projection-first layer 2.
// ============================================================================

#define NN 50000
#define EE 800000
#define FD 64

#define SB 1024
#define NSB ((NN + SB - 1) / SB)   // 49

// ---------------- device scratch (static: no allocations allowed) ----------
__device__ float  g_dinv[NN];
__device__ int    g_cnt[NN];
__device__ int    g_rank[EE];
__device__ int    g_rowptr[NN + 1];
__device__ int    g_bsum[NSB];
__device__ int    g_boff[NSB];
__device__ int2   g_edge[EE];     // (src, ea-bits) then (src, w-bits)
__device__ __half g_Xh[NN * FD];
__device__ __half g_T1h[NN * FD];
__device__ __half g_T2h[NN * FD];
__device__ __half g_G1h[NN * FD];
__device__ __half g_G2h[NN * FD];
__device__ float  g_s0[NN];       // G2 @ W2[0]
__device__ float  g_s1[NN];       // G2 @ W2[1]
__device__ float  g_s2[NN];       // G2 @ W2[2]
__device__ float  g_u[NN];        // s1 + A s2

#define HB_X  0
#define HB_T1 1
#define HB_T2 2
#define HB_G1 3
#define HB_G2 4
__device__ __forceinline__ __half* hbuf_sel(int s) {
    switch (s) {
        case HB_X:  return g_Xh;
        case HB_T1: return g_T1h;
        case HB_T2: return g_T2h;
        case HB_G1: return g_G1h;
        default:    return g_G2h;
    }
}

#define VEC_S0 0
#define VEC_S1 1
#define VEC_S2 2
#define VEC_U  3
__device__ __forceinline__ float* vec_sel(int s) {
    switch (s) {
        case VEC_S0: return g_s0;
        case VEC_S1: return g_s1;
        case VEC_S2: return g_s2;
        default:     return g_u;
    }
}

// ---------------- Threefry-2x32 (JAX-compatible, 20 rounds) ----------------
__host__ __device__ __forceinline__ unsigned tf_rotl(unsigned x, int d) {
    return (x << d) | (x >> (32 - d));
}

__host__ __device__ __forceinline__ void tf2x32(unsigned k0, unsigned k1,
                                                unsigned x0, unsigned x1,
                                                unsigned& o0, unsigned& o1) {
    const unsigned ks2 = k0 ^ k1 ^ 0x1BD11BDAu;
    unsigned v0 = x0 + k0;
    unsigned v1 = x1 + k1;
#define TF_R4(a, b, c, d)                                   \
    v0 += v1; v1 = tf_rotl(v1, a); v1 ^= v0;                \
    v0 += v1; v1 = tf_rotl(v1, b); v1 ^= v0;                \
    v0 += v1; v1 = tf_rotl(v1, c); v1 ^= v0;                \
    v0 += v1; v1 = tf_rotl(v1, d); v1 ^= v0;
    TF_R4(13, 15, 26, 6);  v0 += k1;  v1 += ks2 + 1u;
    TF_R4(17, 29, 16, 24); v0 += ks2; v1 += k0 + 2u;
    TF_R4(13, 15, 26, 6);  v0 += k0;  v1 += k1 + 3u;
    TF_R4(17, 29, 16, 24); v0 += k1;  v1 += ks2 + 4u;
    TF_R4(13, 15, 26, 6);  v0 += ks2; v1 += k0 + 5u;
#undef TF_R4
    o0 = v0;
    o1 = v1;
}

// dropout(0.5) + PReLU on a single value at flat index i
__device__ __forceinline__ float act_apply(float h, unsigned i,
                                           unsigned k0, unsigned k1, float a) {
    unsigned b1, b2;
    tf2x32(k0, k1, 0u, i, b1, b2);
    unsigned bits = b1 ^ b2;
    h = (bits & 0x80000000u) ? 0.0f : 2.0f * h;
    return (h >= 0.0f) ? h : a * h;
}

// ---------------- graph preprocessing ---------------------------------------
__device__ __forceinline__ int clamp_node(int v) {
    return (v < 0) ? 0 : ((v >= NN) ? NN - 1 : v);
}

__global__ void zero_kernel() {
    int i = blockIdx.x * blockDim.x + threadIdx.x;
    if (i < NN) g_cnt[i] = 0;
}

// single atomic pass: count occurrences AND record each edge's bucket rank
__global__ void count_kernel(const int* __restrict__ ei) {
    int e = blockIdx.x * blockDim.x + threadIdx.x;
    if (e >= EE) return;
    int c = clamp_node(ei[EE + e]);  // col = target
    g_rank[e] = atomicAdd(&g_cnt[c], 1);
}

// ---- scans (warp-shuffle based) ----
__global__ void scan1_kernel() {  // grid NSB, block SB: block sums
    __shared__ int ws[32];
    int i = blockIdx.x * SB + threadIdx.x;
    int v = (i < NN) ? g_cnt[i] : 0;
    int lane = threadIdx.x & 31, wid = threadIdx.x >> 5;
#pragma unroll
    for (int off = 16; off; off >>= 1) v += __shfl_down_sync(0xFFFFFFFFu, v, off);
    if (lane == 0) ws[wid] = v;
    __syncthreads();
    if (wid == 0) {
        int w = ws[lane];
#pragma unroll
        for (int off = 16; off; off >>= 1) w += __shfl_down_sync(0xFFFFFFFFu, w, off);
        if (lane == 0) g_bsum[blockIdx.x] = w;
    }
}

__global__ void scan2_kernel() {  // 1 block of 64: scan block sums
    __shared__ int sh[64];
    int t = threadIdx.x;
    int v = (t < NSB) ? g_bsum[t] : 0;
    sh[t] = v;
    __syncthreads();
    for (int off = 1; off < 64; off <<= 1) {
        int u = (t >= off) ? sh[t - off] : 0;
        __syncthreads();
        sh[t] += u;
        __syncthreads();
    }
    if (t < NSB) g_boff[t] = sh[t] - v;   // exclusive
    if (t == 63) g_rowptr[NN] = sh[63];   // total (= EE)
}

__global__ void scan3_kernel() {  // grid NSB, block SB: local excl scan + off
    __shared__ int ws[32];
    int i = blockIdx.x * SB + threadIdx.x;
    int v = (i < NN) ? g_cnt[i] : 0;
    int lane = threadIdx.x & 31, wid = threadIdx.x >> 5;
    int x = v;
#pragma unroll
    for (int off = 1; off < 32; off <<= 1) {
        int y = __shfl_up_sync(0xFFFFFFFFu, x, off);
        if (lane >= off) x += y;
    }
    if (lane == 31) ws[wid] = x;
    __syncthreads();
    if (wid == 0) {
        int w = ws[lane];
#pragma unroll
        for (int off = 1; off < 32; off <<= 1) {
            int y = __shfl_up_sync(0xFFFFFFFFu, w, off);
            if (lane >= off) w += y;
        }
        ws[lane] = w;
    }
    __syncthreads();
    int prefix = (wid > 0) ? ws[wid - 1] : 0;
    if (i < NN) g_rowptr[i] = g_boff[blockIdx.x] + prefix + x - v;  // exclusive
}

// scatter (src, ea) into col-sorted order -- NO atomics (rank precomputed)
__global__ void scatter_kernel(const int* __restrict__ ei,
                               const float* __restrict__ ea) {
    int e = blockIdx.x * blockDim.x + threadIdx.x;
    if (e >= EE) return;
    int r = clamp_node(ei[e]);
    int c = clamp_node(ei[EE + e]);
    int p = g_rowptr[c] + g_rank[e];
    if (p < 0) p = 0;
    if (p >= EE) p = EE - 1;
    g_edge[p] = make_int2(r, __float_as_int(ea[e]));
}

// segment-sum degree (reference index order) -> dinv; no atomics
__global__ void segdinv_kernel() {
    int n = blockIdx.x * blockDim.x + threadIdx.x;
    if (n >= NN) return;
    int s = g_rowptr[n];
    int e = g_rowptr[n + 1];
    float d = 0.0f;
    for (int j = s; j < e; j++) d += __int_as_float(g_edge[j].y);
    g_dinv[n] = (d > 0.0f) ? rsqrtf(fmaxf(d, 1e-12f)) : 0.0f;
}

// rewrite ea -> dinv[src] * ea * dinv[col] in place
__global__ void wfix_kernel() {
    int n = blockIdx.x * blockDim.x + threadIdx.x;
    if (n >= NN) return;
    int s = g_rowptr[n];
    int e = g_rowptr[n + 1];
    float dc = g_dinv[n];
    for (int j = s; j < e; j++) {
        int2 ed = g_edge[j];
        float w = g_dinv[ed.x] * __int_as_float(ed.y) * dc;
        g_edge[j].y = __float_as_int(w);
    }
}

// ---------------- x (fp32) -> Xh (fp16) -------------------------------------
__global__ void cvt_kernel(const float* __restrict__ x) {
    int i = blockIdx.x * blockDim.x + threadIdx.x;
    if (i >= NN * (FD / 2)) return;
    float2 v = ((const float2*)x)[i];
    ((__half2*)g_Xh)[i] = __float22half2_rn(v);
}

// ---------------- SpMM: 8 lanes per node, uint4 (8 halves) per lane --------
__device__ __forceinline__ void hfma8(float* acc, uint4 v, float w) {
    float2 f;
    f = __half22float2(*(__half2*)&v.x); acc[0] += w * f.x; acc[1] += w * f.y;
    f = __half22float2(*(__half2*)&v.y); acc[2] += w * f.x; acc[3] += w * f.y;
    f = __half22float2(*(__half2*)&v.z); acc[4] += w * f.x; acc[5] += w * f.y;
    f = __half22float2(*(__half2*)&v.w); acc[6] += w * f.x; acc[7] += w * f.y;
}

__global__ void spmmh_kernel(int in_sel, int out_sel) {
    int t = blockIdx.x * blockDim.x + threadIdx.x;
    int n = t >> 3;            // node
    int lane = t & 7;
    if (n >= NN) return;
    const uint4* __restrict__ hin = (const uint4*)hbuf_sel(in_sel);  // 8/row
    uint4* __restrict__ hout = (uint4*)hbuf_sel(out_sel);
    int s = g_rowptr[n];
    int e = g_rowptr[n + 1];
    float acc[8] = {0.f, 0.f, 0.f, 0.f, 0.f, 0.f, 0.f, 0.f};
    int j = s;
    for (; j + 4 <= e; j += 4) {
        int2 e0 = g_edge[j];
        int2 e1 = g_edge[j + 1];
        int2 e2 = g_edge[j + 2];
        int2 e3 = g_edge[j + 3];
        uint4 v0 = __ldg(&hin[e0.x * 8 + lane]);
        uint4 v1 = __ldg(&hin[e1.x * 8 + lane]);
        uint4 v2 = __ldg(&hin[e2.x * 8 + lane]);
        uint4 v3 = __ldg(&hin[e3.x * 8 + lane]);
        hfma8(acc, v0, __int_as_float(e0.y));
        hfma8(acc, v1, __int_as_float(e1.y));
        hfma8(acc, v2, __int_as_float(e2.y));
        hfma8(acc, v3, __int_as_float(e3.y));
    }
    for (; j < e; j++) {
        int2 ed = g_edge[j];
        uint4 v = __ldg(&hin[ed.x * 8 + lane]);
        hfma8(acc, v, __int_as_float(ed.y));
    }
    uint4 o;
    *(__half2*)&o.x = __floats2half2_rn(acc[0], acc[1]);
    *(__half2*)&o.y = __floats2half2_rn(acc[2], acc[3]);
    *(__half2*)&o.z = __floats2half2_rn(acc[4], acc[5]);
    *(__half2*)&o.w = __floats2half2_rn(acc[6], acc[7]);
    hout[n * 8 + lane] = o;
}

// ---------------- fused dense + dropout/PReLU (half in, half out) ----------
// Register-tiled: 4 nodes x 4 cols per thread (smem weight loads amortized).
#define DNB 64  // nodes per block (256 threads: 16 slots x 4 nodes, 16 col-thr)
__global__ void dense64_kernel(int h_sel,
                               const float* __restrict__ W,  // (3,64,64)
                               int out_sel,
                               const float* __restrict__ a_ptr,
                               unsigned k0, unsigned k1) {
    __shared__ float sW[3 * 64 * 64];
    {
        const float4* Wv = (const float4*)W;
        float4* sWv = (float4*)sW;
        for (int i = threadIdx.x; i < 3 * 64 * 16; i += 256) sWv[i] = Wv[i];
    }
    __syncthreads();
    int slot = threadIdx.x >> 4;           // 0..15
    int c0 = (threadIdx.x & 15) * 4;       // output col base
    int n0 = blockIdx.x * DNB + slot * 4;  // 4 consecutive nodes
    int nn0 = clamp_node(n0);
    int nn1 = clamp_node(n0 + 1);
    int nn2 = clamp_node(n0 + 2);
    int nn3 = clamp_node(n0 + 3);
    const __half2* __restrict__ hb  = (const __half2*)hbuf_sel(h_sel);
    const __half2* __restrict__ t1b = (const __half2*)g_T1h;
    const __half2* __restrict__ t2b = (const __half2*)g_T2h;
    const __half2* h0 = hb + nn0 * 32, *h1 = hb + nn1 * 32,
                 * h2 = hb + nn2 * 32, *h3 = hb + nn3 * 32;
    const __half2* p0 = t1b + nn0 * 32, *p1 = t1b + nn1 * 32,
                 * p2 = t1b + nn2 * 32, *p3 = t1b + nn3 * 32;
    const __half2* q0 = t2b + nn0 * 32, *q1 = t2b + nn1 * 32,
                 * q2 = t2b + nn2 * 32, *q3 = t2b + nn3 * 32;
    float4 acc0 = {0, 0, 0, 0}, acc1 = {0, 0, 0, 0},
           acc2 = {0, 0, 0, 0}, acc3 = {0, 0, 0, 0};
#pragma unroll 4
    for (int i = 0; i < 32; i++) {
        int ka = 2 * i, kb = 2 * i + 1;
        float4 w0a = *(const float4*)&sW[(0 * 64 + ka) * 64 + c0];
        float4 w0b = *(const float4*)&sW[(0 * 64 + kb) * 64 + c0];
        float4 w1a = *(const float4*)&sW[(1 * 64 + ka) * 64 + c0];
        float4 w1b = *(const float4*)&sW[(1 * 64 + kb) * 64 + c0];
        float4 w2a = *(const float4*)&sW[(2 * 64 + ka) * 64 + c0];
        float4 w2b = *(const float4*)&sW[(2 * 64 + kb) * 64 + c0];
#define DO_NODE(acc, hp, pp, qp)                                              \
        {                                                                     \
            float2 hv  = __half22float2(__ldg(&hp[i]));                       \
            float2 t1v = __half22float2(__ldg(&pp[i]));                       \
            float2 t2v = __half22float2(__ldg(&qp[i]));                       \
            acc.x += hv.x * w0a.x + hv.y * w0b.x + t1v.x * w1a.x              \
                   + t1v.y * w1b.x + t2v.x * w2a.x + t2v.y * w2b.x;           \
            acc.y += hv.x * w0a.y + hv.y * w0b.y + t1v.x * w1a.y              \
                   + t1v.y * w1b.y + t2v.x * w2a.y + t2v.y * w2b.y;           \
            acc.z += hv.x * w0a.z + hv.y * w0b.z + t1v.x * w1a.z              \
                   + t1v.y * w1b.z + t2v.x * w2a.z + t2v.y * w2b.z;           \
            acc.w += hv.x * w0a.w + hv.y * w0b.w + t1v.x * w1a.w              \
                   + t1v.y * w1b.w + t2v.x * w2a.w + t2v.y * w2b.w;           \
        }
        DO_NODE(acc0, h0, p0, q0)
        DO_NODE(acc1, h1, p1, q1)
        DO_NODE(acc2, h2, p2, q2)
        DO_NODE(acc3, h3, p3, q3)
#undef DO_NODE
    }
    float a = __ldg(&a_ptr[0]);
    __half2* outb = (__half2*)hbuf_sel(out_sel);
#define EMIT(acc, node)                                                       \
    if ((node) < NN) {                                                        \
        unsigned base = (unsigned)((node) * FD + c0);                         \
        float r0 = act_apply(acc.x, base + 0u, k0, k1, a);                    \
        float r1 = act_apply(acc.y, base + 1u, k0, k1, a);                    \
        float r2 = act_apply(acc.z, base + 2u, k0, k1, a);                    \
        float r3 = act_apply(acc.w, base + 3u, k0, k1, a);                    \
        __half2* op = outb + (node) * 32 + c0 / 2;                            \
        op[0] = __floats2half2_rn(r0, r1);                                    \
        op[1] = __floats2half2_rn(r2, r3);                                    \
    }
    EMIT(acc0, n0)
    EMIT(acc1, n0 + 1)
    EMIT(acc2, n0 + 2)
    EMIT(acc3, n0 + 3)
#undef EMIT
}

// ---------------- 3-way projection: s_k[n] = G2h[n,:] @ W2[k,:,0] ----------
__global__ void proj3_kernel(const float* __restrict__ W) {  // (3,64,1)
    int warp = (blockIdx.x * blockDim.x + threadIdx.x) >> 5;
    int lane = threadIdx.x & 31;
    if (warp >= NN) return;
    int i0 = lane * 2;
    float2 g = __half22float2(((const __half2*)g_G2h)[warp * 32 + lane]);
    float s0 = g.x * __ldg(&W[i0])       + g.y * __ldg(&W[i0 + 1]);
    float s1 = g.x * __ldg(&W[64 + i0])  + g.y * __ldg(&W[64 + i0 + 1]);
    float s2 = g.x * __ldg(&W[128 + i0]) + g.y * __ldg(&W[128 + i0 + 1]);
#pragma unroll
    for (int off = 16; off; off >>= 1) {
        s0 += __shfl_down_sync(0xFFFFFFFFu, s0, off);
        s1 += __shfl_down_sync(0xFFFFFFFFu, s1, off);
        s2 += __shfl_down_sync(0xFFFFFFFFu, s2, off);
    }
    if (lane == 0) {
        g_s0[warp] = s0;
        g_s1[warp] = s1;
        g_s2[warp] = s2;
    }
}

// ---------------- 1-wide SpMM: out[n] = add[n] + sum w_e * vin[src_e] -------
__global__ void spmm1_kernel(int in_sel, int add_sel, int out_sel,
                             float* __restrict__ out_ext) {
    int n = blockIdx.x * blockDim.x + threadIdx.x;
    if (n >= NN) return;
    const float* __restrict__ vin = vec_sel(in_sel);
    float* __restrict__ vout = (out_sel < 0) ? out_ext : vec_sel(out_sel);
    int s = g_rowptr[n];
    int e = g_rowptr[n + 1];
    float acc = 0.0f;
    int j = s;
    for (; j + 4 <= e; j += 4) {
        int2 e0 = g_edge[j];
        int2 e1 = g_edge[j + 1];
        int2 e2 = g_edge[j + 2];
        int2 e3 = g_edge[j + 3];
        float v0 = __ldg(&vin[e0.x]);
        float v1 = __ldg(&vin[e1.x]);
        float v2 = __ldg(&vin[e2.x]);
        float v3 = __ldg(&vin[e3.x]);
        acc += __int_as_float(e0.y) * v0 + __int_as_float(e1.y) * v1
             + __int_as_float(e2.y) * v2 + __int_as_float(e3.y) * v3;
    }
    for (; j < e; j++) {
        int2 ed = g_edge[j];
        acc += __int_as_float(ed.y) * __ldg(&vin[ed.x]);
    }
    vout[n] = vec_sel(add_sel)[n] + acc;
}

// ============================================================================
extern "C" void kernel_launch(void* const* d_in, const int* in_sizes, int n_in,
                              void* d_out, int out_size) {
    const float* x  = (const float*)d_in[0];
    const int*   ei = (const int*)d_in[1];     // int32: JAX x64-disabled
    const float* ea = (const float*)d_in[2];
    const float* W0 = (const float*)d_in[3];
    const float* W1 = (const float*)d_in[4];
    const float* W2 = (const float*)d_in[5];
    const float* a0 = (const float*)d_in[6];
    const float* a1 = (const float*)d_in[7];
    float* out = (float*)d_out;

    // host-side Threefry: dropout subkeys from jax.random.key(42) = (0, 42)
    unsigned dk0_0, dk0_1, dk1_0, dk1_1;
    tf2x32(0u, 42u, 0u, 0u, dk0_0, dk0_1);
    tf2x32(0u, 42u, 0u, 1u, dk1_0, dk1_1);

    const int TB = 256;
    const int gN  = (NN + TB - 1) / TB;
    const int gE  = (EE + TB - 1) / TB;
    const int gS  = (NN * 8 + TB - 1) / TB;    // 8 lanes per node (spmmh)
    const int gW  = (NN * 32 + TB - 1) / TB;   // warp per node (proj3)
    const int gC  = (NN * (FD / 2) + TB - 1) / TB;
    const int gD  = (NN + DNB - 1) / DNB;      // 64 nodes per block

    // ---- graph preprocessing (CSR by target; 1 atomic per edge total) ----
    zero_kernel<<<gN, TB>>>();
    count_kernel<<<gE, TB>>>(ei);
    scan1_kernel<<<NSB, SB>>>();
    scan2_kernel<<<1, 64>>>();
    scan3_kernel<<<NSB, SB>>>();
    scatter_kernel<<<gE, TB>>>(ei, ea);
    segdinv_kernel<<<gN, TB>>>();
    wfix_kernel<<<gN, TB>>>();
    cvt_kernel<<<gC, TB>>>(x);

    // ---- layer 0: Xh -> G1h ----
    spmmh_kernel<<<gS, TB>>>(HB_X, HB_T1);
    spmmh_kernel<<<gS, TB>>>(HB_T1, HB_T2);
    dense64_kernel<<<gD, TB>>>(HB_X, W0, HB_G1, a0, dk0_0, dk0_1);

    // ---- layer 1: G1h -> G2h ----
    spmmh_kernel<<<gS, TB>>>(HB_G1, HB_T1);
    spmmh_kernel<<<gS, TB>>>(HB_T1, HB_T2);
    dense64_kernel<<<gD, TB>>>(HB_G1, W1, HB_G2, a1, dk1_0, dk1_1);

    // ---- layer 2 (projection-first): out = s0 + A(s1 + A s2) ----
    proj3_kernel<<<gW, TB>>>(W2);
    spmm1_kernel<<<gN, TB>>>(VEC_S2, VEC_S1, VEC_U, nullptr);  // u = s1 + A s2
    spmm1_kernel<<<gN, TB>>>(VEC_U, VEC_S0, -1, out);          // out = s0 + A u
}